// round 3
// baseline (speedup 1.0000x reference)
#include <cuda_runtime.h>
#include <math.h>

#define Bv 1024
#define Sv 2048
#define Dv 64
#define Hv 4
#define HDv 16

// Scratch (no cudaMalloc allowed) — static device globals.
__device__ float g_hbuf[Bv * 128];   // relu(value @ w_a1.T + b_a1)
__device__ float g_wvbuf[Bv * Dv];   // write_value per batch
__device__ float g_ebuf[(size_t)Bv * Sv]; // exp(logits)
__device__ float g_invd[Bv];         // 1/sum(exp)

// ---------------------------------------------------------------------------
// K1: per-batch attention pass.
// One CTA per batch. 256 threads = 8 warps; each warp splits into 4 groups of
// 8 lanes; each group processes one scratchpad row per iteration (64 iters of
// 32 rows CTA-wide... actually 32 rows per iteration across the CTA).
// Produces: g_hbuf[b], g_wvbuf[b].
// ---------------------------------------------------------------------------
__global__ __launch_bounds__(256, 2) void k1_attn(
    const float* __restrict__ query, const float* __restrict__ sp,
    const float* __restrict__ wq, const float* __restrict__ wk,
    const float* __restrict__ wv, const float* __restrict__ bq,
    const float* __restrict__ bk, const float* __restrict__ bv,
    const float* __restrict__ wo, const float* __restrict__ bo,
    const float* __restrict__ w_write, const float* __restrict__ b_write,
    const float* __restrict__ w_a1, const float* __restrict__ b_a1)
{
    __shared__ float s_q[Dv];
    __shared__ float s_qv[Dv];
    __shared__ float s_qk[Hv * Dv];
    __shared__ float s_c[Hv];
    __shared__ float s_pl[32 * Hv];
    __shared__ float s_u[8448];      // reused: staged 64x64 weights (stride 65), partial u's
    __shared__ float s_wvec[Hv * Dv];
    __shared__ float s_ctx[Dv];
    __shared__ float s_val[Dv];

    const int b = blockIdx.x;
    const int t = threadIdx.x;

    // --- q projection: q_vec = wq @ query_b + bq ---
    if (t < Dv) s_q[t] = query[(size_t)b * Dv + t];
    for (int idx = t; idx < Dv * Dv; idx += 256)
        s_u[(idx >> 6) * 65 + (idx & 63)] = wq[idx];
    __syncthreads();
    if (t < Dv) {
        float acc = bq[t];
#pragma unroll
        for (int j = 0; j < Dv; j++) acc += s_u[t * 65 + j] * s_q[j];
        s_qv[t] = acc;
    }
    __syncthreads();

    // --- folded score vectors: qk_h[j] = 0.25 * sum_t q[16h+t]*wk[16h+t, j] ---
    {
        const int h = t >> 6, j = t & 63;
        float acc = 0.f;
#pragma unroll
        for (int tt = 0; tt < HDv; tt++)
            acc += s_qv[h * HDv + tt] * wk[(h * HDv + tt) * Dv + j];
        s_qk[h * Dv + j] = 0.25f * acc;
        if (t < Hv) {
            float c = 0.f;
#pragma unroll
            for (int tt = 0; tt < HDv; tt++) c += s_qv[t * HDv + tt] * bk[t * HDv + tt];
            s_c[t] = 0.25f * c;
        }
    }
    __syncthreads();

    const int warp = t >> 5, lane = t & 31;
    const int g = lane >> 3, sub = lane & 7;
    const int d0 = sub * 8;

    float qkr[Hv][8];
#pragma unroll
    for (int h = 0; h < Hv; h++)
#pragma unroll
        for (int k = 0; k < 8; k++) qkr[h][k] = s_qk[h * Dv + d0 + k];
    float cst[Hv];
#pragma unroll
    for (int h = 0; h < Hv; h++) cst[h] = s_c[h];

    float u[Hv][8];
    float ls[Hv];
#pragma unroll
    for (int h = 0; h < Hv; h++) {
        ls[h] = 0.f;
#pragma unroll
        for (int k = 0; k < 8; k++) u[h][k] = 0.f;
    }

    const float4* base = (const float4*)(sp + (size_t)b * Sv * Dv);
    const int row0 = warp * 4 + g;
    const float4* p0 = base + (size_t)row0 * 16 + sub * 2;  // 512 float4 per 32-row step

    // Process one row (x0,x1 = this lane's 8 dims). Scores small (~N(0,0.16^2)),
    // so exp without max-subtraction is safe and exact for softmax.
    auto process = [&](float4 x0, float4 x1) {
        float xa[8] = {x0.x, x0.y, x0.z, x0.w, x1.x, x1.y, x1.z, x1.w};
        float sc[Hv];
#pragma unroll
        for (int h = 0; h < Hv; h++) {
            float a = 0.f;
#pragma unroll
            for (int k = 0; k < 8; k++) a += qkr[h][k] * xa[k];
            sc[h] = a;
        }
#pragma unroll
        for (int off = 1; off < 8; off <<= 1)
#pragma unroll
            for (int h = 0; h < Hv; h++)
                sc[h] += __shfl_xor_sync(0xffffffffu, sc[h], off);
#pragma unroll
        for (int h = 0; h < Hv; h++) {
            float p = __expf(sc[h] + cst[h]);
            ls[h] += p;
#pragma unroll
            for (int k = 0; k < 8; k++) u[h][k] += p * xa[k];
        }
    };

    // Software-pipelined, unroll-by-2 (2 KB in flight per warp).
    float4 a0 = p0[0], a1 = p0[1];
    const float4* p1 = p0 + 512;
    float4 b0 = p1[0], b1 = p1[1];
#pragma unroll 1
    for (int it = 0; it < 64; it += 2) {
        const int itn = (it + 2 < 64) ? (it + 2) : 0;  // wrap: harmless cached reload on last iter
        const float4* pc = p0 + (size_t)itn * 512;
        float4 c0 = pc[0], c1 = pc[1];
        const float4* pd = pc + 512;
        float4 e0 = pd[0], e1 = pd[1];
        process(a0, a1);
        process(b0, b1);
        a0 = c0; a1 = c1; b0 = e0; b1 = e1;
    }

    // --- combine 32 group partials ---
    const int pg = warp * 4 + g;
    if (sub == 0) {
#pragma unroll
        for (int h = 0; h < Hv; h++) s_pl[pg * 4 + h] = ls[h];
    }
#pragma unroll
    for (int h = 0; h < Hv; h++)
#pragma unroll
        for (int k = 0; k < 8; k++)
            s_u[(pg * 4 + h) * 64 + d0 + k] = u[h][k];
    __syncthreads();
    {
        const int h = t >> 6, d = t & 63;
        float U = 0.f;
#pragma unroll
        for (int p = 0; p < 32; p++) U += s_u[(p * 4 + h) * 64 + d];
        float L = 0.f;
#pragma unroll
        for (int p = 0; p < 32; p++) L += s_pl[p * 4 + h];
        s_wvec[h * 64 + d] = U / L;   // attn-weighted mean of sp rows
    }
    __syncthreads();

    // --- ctx = Wv @ wvec + bv ---
    for (int idx = t; idx < Dv * Dv; idx += 256)
        s_u[(idx >> 6) * 65 + (idx & 63)] = wv[idx];
    __syncthreads();
    if (t < Dv) {
        float acc = bv[t];
        const int h = t >> 4;
#pragma unroll
        for (int j = 0; j < Dv; j++) acc += s_u[t * 65 + j] * s_wvec[h * 64 + j];
        s_ctx[t] = acc;
    }
    __syncthreads();

    // --- value = Wo @ ctx + bo ---
    for (int idx = t; idx < Dv * Dv; idx += 256)
        s_u[(idx >> 6) * 65 + (idx & 63)] = wo[idx];
    __syncthreads();
    if (t < Dv) {
        float acc = bo[t];
#pragma unroll
        for (int j = 0; j < Dv; j++) acc += s_u[t * 65 + j] * s_ctx[j];
        s_val[t] = acc;
    }
    __syncthreads();

    // --- h = relu(w_a1 @ value + b_a1)  (128 outputs) ---
    for (int idx = t; idx < 128 * Dv; idx += 256)
        s_u[(idx >> 6) * 65 + (idx & 63)] = w_a1[idx];
    __syncthreads();
    if (t < 128) {
        float acc = b_a1[t];
#pragma unroll
        for (int j = 0; j < Dv; j++) acc += s_u[t * 65 + j] * s_val[j];
        g_hbuf[(size_t)b * 128 + t] = fmaxf(acc, 0.f);
    }
    __syncthreads();

    // --- write_value = w_write @ value + b_write ---
    for (int idx = t; idx < Dv * Dv; idx += 256)
        s_u[(idx >> 6) * 65 + (idx & 63)] = w_write[idx];
    __syncthreads();
    if (t < Dv) {
        float acc = b_write[t];
#pragma unroll
        for (int j = 0; j < Dv; j++) acc += s_u[t * 65 + j] * s_val[j];
        g_wvbuf[(size_t)b * Dv + t] = acc;
    }
}

// ---------------------------------------------------------------------------
// K2: address logits GEMM (1024 x 2048 x 128) + exp + per-batch denominator.
// 128 CTAs x 8 batches; thread computes an 8s x 8b register tile; w_a2 rows
// read 32B-contiguous per lane (full sector use), h-rows broadcast from smem.
// ---------------------------------------------------------------------------
__global__ __launch_bounds__(256) void k2_addr(const float* __restrict__ w_a2,
                                               const float* __restrict__ b_a2)
{
    const int b0 = blockIdx.x * 8;
    const int t = threadIdx.x;
    __shared__ float hs[8 * 128];
    __shared__ float sden[8];

    for (int idx = t; idx < 1024; idx += 256) hs[idx] = g_hbuf[(size_t)b0 * 128 + idx];
    if (t < 8) sden[t] = 0.f;
    __syncthreads();

    float acc[8][8];
#pragma unroll
    for (int r = 0; r < 8; r++)
#pragma unroll
        for (int bb = 0; bb < 8; bb++) acc[r][bb] = 0.f;

    const float4* w4 = (const float4*)w_a2;
    const float4* h4 = (const float4*)hs;
#pragma unroll 1
    for (int k8 = 0; k8 < 16; k8++) {
        float4 ha[8], hb[8];
#pragma unroll
        for (int bb = 0; bb < 8; bb++) {
            ha[bb] = h4[bb * 32 + 2 * k8];
            hb[bb] = h4[bb * 32 + 2 * k8 + 1];
        }
#pragma unroll
        for (int r = 0; r < 8; r++) {
            const int s = t + 256 * r;
            float4 wa = w4[(size_t)s * 32 + 2 * k8];
            float4 wb = w4[(size_t)s * 32 + 2 * k8 + 1];
#pragma unroll
            for (int bb = 0; bb < 8; bb++) {
                acc[r][bb] += wa.x * ha[bb].x + wa.y * ha[bb].y +
                              wa.z * ha[bb].z + wa.w * ha[bb].w +
                              wb.x * hb[bb].x + wb.y * hb[bb].y +
                              wb.z * hb[bb].z + wb.w * hb[bb].w;
            }
        }
    }

    float psum[8];
#pragma unroll
    for (int bb = 0; bb < 8; bb++) psum[bb] = 0.f;
#pragma unroll
    for (int r = 0; r < 8; r++) {
        const int s = t + 256 * r;
        const float ba = b_a2[s];
#pragma unroll
        for (int bb = 0; bb < 8; bb++) {
            float e = __expf(acc[r][bb] + ba);   // logits small -> safe w/o max-sub
            g_ebuf[(size_t)(b0 + bb) * Sv + s] = e;
            psum[bb] += e;
        }
    }
#pragma unroll
    for (int off = 16; off; off >>= 1)
#pragma unroll
        for (int bb = 0; bb < 8; bb++)
            psum[bb] += __shfl_xor_sync(0xffffffffu, psum[bb], off);
    if ((t & 31) == 0) {
#pragma unroll
        for (int bb = 0; bb < 8; bb++) atomicAdd(&sden[bb], psum[bb]);
    }
    __syncthreads();
    if (t < 8) g_invd[b0 + t] = 1.f / sden[t];
}

// ---------------------------------------------------------------------------
// K3: out[b,s,:] = sp[b,s,:] + (write_value[b,:] - sp[b,s,:]) * a[b,s]
// Pure stream: 512 MB read + 512 MB write. One float4 per thread.
// ---------------------------------------------------------------------------
__global__ __launch_bounds__(256) void k3_write(const float* __restrict__ sp,
                                                float* __restrict__ out)
{
    const size_t gi = (size_t)blockIdx.x * 256 + threadIdx.x;  // float4 index
    const size_t row = gi >> 4;
    const int b = (int)(row >> 11);
    const float a = g_ebuf[row] * g_invd[b];
    const float4 x = ((const float4*)sp)[gi];
    const float4 w = ((const float4*)g_wvbuf)[(size_t)b * 16 + (gi & 15)];
    float4 o;
    o.x = x.x + (w.x - x.x) * a;
    o.y = x.y + (w.y - x.y) * a;
    o.z = x.z + (w.z - x.z) * a;
    o.w = x.w + (w.w - x.w) * a;
    ((float4*)out)[gi] = o;
}

extern "C" void kernel_launch(void* const* d_in, const int* in_sizes, int n_in,
                              void* d_out, int out_size)
{
    (void)in_sizes; (void)n_in; (void)out_size;
    const float* query   = (const float*)d_in[0];
    const float* sp      = (const float*)d_in[1];
    const float* wq      = (const float*)d_in[2];
    const float* wk      = (const float*)d_in[3];
    const float* wv      = (const float*)d_in[4];
    const float* bq      = (const float*)d_in[5];
    const float* bk      = (const float*)d_in[6];
    const float* bv      = (const float*)d_in[7];
    const float* wo      = (const float*)d_in[8];
    const float* bo      = (const float*)d_in[9];
    const float* w_write = (const float*)d_in[10];
    const float* b_write = (const float*)d_in[11];
    const float* w_a1    = (const float*)d_in[12];
    const float* b_a1    = (const float*)d_in[13];
    const float* w_a2    = (const float*)d_in[14];
    const float* b_a2    = (const float*)d_in[15];
    float* out = (float*)d_out;

    k1_attn<<<Bv, 256>>>(query, sp, wq, wk, wv, bq, bk, bv, wo, bo,
                         w_write, b_write, w_a1, b_a1);
    k2_addr<<<Bv / 8, 256>>>(w_a2, b_a2);
    k3_write<<<(Bv * Sv * Dv / 4) / 256, 256>>>(sp, out);
}

// round 5
// speedup vs baseline: 1.0806x; 1.0806x over previous
#include <cuda_runtime.h>
#include <math.h>

#define Bv 1024
#define Sv 2048
#define Dv 64
#define Hv 4
#define HDv 16

// Scratch (no cudaMalloc allowed) — static device globals.
__device__ float g_hbuf[Bv * 128];        // relu(value @ w_a1.T + b_a1)
__device__ float g_wvbuf[Bv * Dv];        // write_value per batch
__device__ float g_ebuf[(size_t)Bv * Sv]; // NORMALIZED address a[b,s]

__device__ __forceinline__ void cp_async16(void* smem_dst, const void* gsrc) {
    unsigned sd = (unsigned)__cvta_generic_to_shared(smem_dst);
    asm volatile("cp.async.cg.shared.global [%0], [%1], 16;\n" :: "r"(sd), "l"(gsrc));
}
#define CP_COMMIT() asm volatile("cp.async.commit_group;\n" ::: "memory")
#define CP_WAIT1()  asm volatile("cp.async.wait_group 1;\n" ::: "memory")

// ---------------------------------------------------------------------------
// K1: per-batch attention pass. One CTA per batch, 256 threads.
// cp.async DOUBLE-buffered 64-row tiles (32KB dynamic smem — fits under the
// 48KB default limit together with ~3.6KB static smem; no attribute call).
// 8 warps x 4 groups of 8 lanes; each group handles rows g', g'+32 per tile.
// Lane 'sub' owns dims {4*sub..4*sub+3} U {32+4*sub..32+4*sub+3} ->
// contiguous 128B per LDS.128 per 8-lane group = conflict-free.
// ---------------------------------------------------------------------------
__global__ __launch_bounds__(256, 2) void k1_attn(
    const float* __restrict__ query, const float* __restrict__ sp,
    const float* __restrict__ wq, const float* __restrict__ wk,
    const float* __restrict__ wv, const float* __restrict__ bq,
    const float* __restrict__ bk, const float* __restrict__ bv,
    const float* __restrict__ wo, const float* __restrict__ bo,
    const float* __restrict__ w_write, const float* __restrict__ b_write,
    const float* __restrict__ w_a1, const float* __restrict__ b_a1)
{
    extern __shared__ float dyn[];   // 2 stages * 64 rows * 64 floats = 8192 floats (32KB)
                                     // aliased as the partial-combine buffer in the epilogue
    __shared__ float s_q[Dv];
    __shared__ float s_qv[Dv];
    __shared__ float s_qk[Hv * Dv];
    __shared__ float s_c[Hv];
    __shared__ float s_pl[32 * Hv];
    __shared__ float s_wvec[Hv * Dv];
    __shared__ float s_ctx[Dv];
    __shared__ float s_val[Dv];

    const int b = blockIdx.x;
    const int t = threadIdx.x;
    const float* spb = sp + (size_t)b * Sv * Dv;

    // ---- issue first 2 tiles immediately (tile = 64 rows = 1024 float4) ----
#pragma unroll
    for (int st = 0; st < 2; st++) {
#pragma unroll
        for (int k = 0; k < 4; k++) {
            int idx = t + k * 256;                       // float4 index in tile
            cp_async16(dyn + (size_t)st * 4096 + idx * 4,
                       spb + (size_t)st * 4096 + idx * 4);
        }
        CP_COMMIT();
    }

    // ---- q projection (reads wq from global/L2) ----
    if (t < Dv) s_q[t] = query[(size_t)b * Dv + t];
    __syncthreads();
    if (t < Dv) {
        float acc = bq[t];
        const float* wr = wq + t * Dv;
#pragma unroll
        for (int j = 0; j < Dv; j++) acc += __ldg(wr + j) * s_q[j];
        s_qv[t] = acc;
    }
    __syncthreads();

    // ---- folded score vectors: qk_h[j] = 0.25 * sum_t qv[16h+t]*wk[16h+t,j] ----
    {
        const int h = t >> 6, j = t & 63;
        float acc = 0.f;
#pragma unroll
        for (int tt = 0; tt < HDv; tt++)
            acc += s_qv[h * HDv + tt] * __ldg(&wk[(h * HDv + tt) * Dv + j]);
        s_qk[h * Dv + j] = 0.25f * acc;
        if (t < Hv) {
            float c = 0.f;
#pragma unroll
            for (int tt = 0; tt < HDv; tt++) c += s_qv[t * HDv + tt] * __ldg(&bk[t * HDv + tt]);
            s_c[t] = 0.25f * c;
        }
    }
    __syncthreads();

    const int warp = t >> 5, lane = t & 31;
    const int g = lane >> 3, sub = lane & 7;
    // lane's dims: k<4 -> 4*sub+k ; k>=4 -> 32+4*sub+(k-4)
    float qkr[Hv][8];
#pragma unroll
    for (int h = 0; h < Hv; h++)
#pragma unroll
        for (int k = 0; k < 8; k++) {
            int d = (k < 4) ? (4 * sub + k) : (32 + 4 * sub + k - 4);
            qkr[h][k] = s_qk[h * Dv + d];
        }
    float cst[Hv];
#pragma unroll
    for (int h = 0; h < Hv; h++) cst[h] = s_c[h];

    float u[Hv][8];
    float ls[Hv];
#pragma unroll
    for (int h = 0; h < Hv; h++) {
        ls[h] = 0.f;
#pragma unroll
        for (int k = 0; k < 8; k++) u[h][k] = 0.f;
    }

    const int rA = warp * 4 + g;        // local row in tile
    const int rB = rA + 32;

    // ---- main loop: 32 tiles of 64 rows, double-buffered ----
#pragma unroll 1
    for (int it = 0; it < 32; it++) {
        const int stage = it & 1;
        CP_WAIT1();
        __syncthreads();

        const float4* tp = (const float4*)(dyn + (size_t)stage * 4096);
        float4 a0 = tp[rA * 16 + sub];
        float4 a1 = tp[rA * 16 + 8 + sub];
        float4 b0 = tp[rB * 16 + sub];
        float4 b1 = tp[rB * 16 + 8 + sub];
        float xA[8] = {a0.x, a0.y, a0.z, a0.w, a1.x, a1.y, a1.z, a1.w};
        float xB[8] = {b0.x, b0.y, b0.z, b0.w, b1.x, b1.y, b1.z, b1.w};

        float scA[Hv], scB[Hv];
#pragma unroll
        for (int h = 0; h < Hv; h++) {
            float sa = 0.f, sb = 0.f;
#pragma unroll
            for (int k = 0; k < 8; k++) {
                sa += qkr[h][k] * xA[k];
                sb += qkr[h][k] * xB[k];
            }
            scA[h] = sa; scB[h] = sb;
        }
#pragma unroll
        for (int off = 1; off < 8; off <<= 1) {
#pragma unroll
            for (int h = 0; h < Hv; h++) {
                scA[h] += __shfl_xor_sync(0xffffffffu, scA[h], off);
                scB[h] += __shfl_xor_sync(0xffffffffu, scB[h], off);
            }
        }
#pragma unroll
        for (int h = 0; h < Hv; h++) {
            float pA = __expf(scA[h] + cst[h]);
            float pB = __expf(scB[h] + cst[h]);
            ls[h] += pA + pB;
#pragma unroll
            for (int k = 0; k < 8; k++) u[h][k] += pA * xA[k] + pB * xB[k];
        }

        __syncthreads();
        // refill this stage with tile it+2 (always commit: uniform group count)
        const int nt = it + 2;
        if (nt < 32) {
#pragma unroll
            for (int k = 0; k < 4; k++) {
                int idx = t + k * 256;
                cp_async16(dyn + (size_t)stage * 4096 + idx * 4,
                           spb + (size_t)nt * 4096 + idx * 4);
            }
        }
        CP_COMMIT();
    }
    __syncthreads();

    // ---- combine 32 group partials (dyn aliased; 8192 floats exactly) ----
    float* s_part = dyn;
    const int pg = warp * 4 + g;
    if (sub == 0) {
#pragma unroll
        for (int h = 0; h < Hv; h++) s_pl[pg * 4 + h] = ls[h];
    }
#pragma unroll
    for (int h = 0; h < Hv; h++)
#pragma unroll
        for (int k = 0; k < 8; k++) {
            int d = (k < 4) ? (4 * sub + k) : (32 + 4 * sub + k - 4);
            s_part[(pg * 4 + h) * 64 + d] = u[h][k];
        }
    __syncthreads();
    {
        const int h = t >> 6, d = t & 63;
        float U = 0.f;
#pragma unroll
        for (int p = 0; p < 32; p++) U += s_part[(p * 4 + h) * 64 + d];
        float L = 0.f;
#pragma unroll
        for (int p = 0; p < 32; p++) L += s_pl[p * 4 + h];
        s_wvec[h * 64 + d] = U / L;   // attn-weighted mean of sp rows
    }
    __syncthreads();

    // ---- tiny per-batch matvec chain (weights straight from global/L2) ----
    if (t < Dv) {
        float acc = bv[t];
        const int h = t >> 4;
        const float* wr = wv + t * Dv;
#pragma unroll
        for (int j = 0; j < Dv; j++) acc += __ldg(wr + j) * s_wvec[h * 64 + j];
        s_ctx[t] = acc;
    }
    __syncthreads();
    if (t < Dv) {
        float acc = bo[t];
        const float* wr = wo + t * Dv;
#pragma unroll
        for (int j = 0; j < Dv; j++) acc += __ldg(wr + j) * s_ctx[j];
        s_val[t] = acc;
    }
    __syncthreads();
    if (t < 128) {
        float acc = b_a1[t];
        const float* wr = w_a1 + t * Dv;
#pragma unroll
        for (int j = 0; j < Dv; j++) acc += __ldg(wr + j) * s_val[j];
        g_hbuf[(size_t)b * 128 + t] = fmaxf(acc, 0.f);
    }
    if (t >= 128 && t < 128 + Dv) {
        const int o = t - 128;
        float acc = b_write[o];
        const float* wr = w_write + o * Dv;
#pragma unroll
        for (int j = 0; j < Dv; j++) acc += __ldg(wr + j) * s_val[j];
        g_wvbuf[(size_t)b * Dv + o] = acc;
    }
}

// ---------------------------------------------------------------------------
// K2: address logits GEMM (1024 x 2048 x 128) + softmax. Writes NORMALIZED
// address a[b,s] into g_ebuf (the CTA owns the full per-batch denominator).
// ---------------------------------------------------------------------------
__global__ __launch_bounds__(256) void k2_addr(const float* __restrict__ w_a2,
                                               const float* __restrict__ b_a2)
{
    const int b0 = blockIdx.x * 8;
    const int t = threadIdx.x;
    __shared__ float hs[8 * 128];
    __shared__ float sden[8];

    for (int idx = t; idx < 1024; idx += 256) hs[idx] = g_hbuf[(size_t)b0 * 128 + idx];
    if (t < 8) sden[t] = 0.f;
    __syncthreads();

    float acc[8][8];
#pragma unroll
    for (int r = 0; r < 8; r++)
#pragma unroll
        for (int bb = 0; bb < 8; bb++) acc[r][bb] = 0.f;

    const float4* w4 = (const float4*)w_a2;
    const float4* h4 = (const float4*)hs;
#pragma unroll 1
    for (int k8 = 0; k8 < 16; k8++) {
        float4 ha[8], hb[8];
#pragma unroll
        for (int bb = 0; bb < 8; bb++) {
            ha[bb] = h4[bb * 32 + 2 * k8];
            hb[bb] = h4[bb * 32 + 2 * k8 + 1];
        }
#pragma unroll
        for (int r = 0; r < 8; r++) {
            const int s = t + 256 * r;
            float4 wa = w4[(size_t)s * 32 + 2 * k8];
            float4 wb = w4[(size_t)s * 32 + 2 * k8 + 1];
#pragma unroll
            for (int bb = 0; bb < 8; bb++) {
                acc[r][bb] += wa.x * ha[bb].x + wa.y * ha[bb].y +
                              wa.z * ha[bb].z + wa.w * ha[bb].w +
                              wb.x * hb[bb].x + wb.y * hb[bb].y +
                              wb.z * hb[bb].z + wb.w * hb[bb].w;
            }
        }
    }

    // pass 1: per-batch exp-sum (logits small -> safe without max-sub)
    float psum[8];
#pragma unroll
    for (int bb = 0; bb < 8; bb++) psum[bb] = 0.f;
#pragma unroll
    for (int r = 0; r < 8; r++) {
        const float ba = b_a2[t + 256 * r];
#pragma unroll
        for (int bb = 0; bb < 8; bb++) psum[bb] += __expf(acc[r][bb] + ba);
    }
#pragma unroll
    for (int off = 16; off; off >>= 1)
#pragma unroll
        for (int bb = 0; bb < 8; bb++)
            psum[bb] += __shfl_xor_sync(0xffffffffu, psum[bb], off);
    if ((t & 31) == 0) {
#pragma unroll
        for (int bb = 0; bb < 8; bb++) atomicAdd(&sden[bb], psum[bb]);
    }
    __syncthreads();

    float inv[8];
#pragma unroll
    for (int bb = 0; bb < 8; bb++) inv[bb] = 1.f / sden[bb];

    // pass 2: recompute exp (deterministic), write normalized a
#pragma unroll
    for (int r = 0; r < 8; r++) {
        const int s = t + 256 * r;
        const float ba = b_a2[s];
#pragma unroll
        for (int bb = 0; bb < 8; bb++)
            g_ebuf[(size_t)(b0 + bb) * Sv + s] = __expf(acc[r][bb] + ba) * inv[bb];
    }
}

// ---------------------------------------------------------------------------
// K3: out[b,s,:] = sp + (write_value - sp) * a[b,s]. Streaming, ILP 2.
// ---------------------------------------------------------------------------
__global__ __launch_bounds__(256) void k3_write(const float* __restrict__ sp,
                                                float* __restrict__ out)
{
    const size_t base = (size_t)blockIdx.x * 512 + threadIdx.x;  // float4 units
#pragma unroll
    for (int j = 0; j < 2; j++) {
        const size_t gi = base + (size_t)j * 256;
        const size_t row = gi >> 4;
        const int b = (int)(row >> 11);
        const float a = __ldg(&g_ebuf[row]);
        const float4 x = __ldcs(((const float4*)sp) + gi);
        const float4 w = __ldg(((const float4*)g_wvbuf) + (size_t)b * 16 + (gi & 15));
        float4 o;
        o.x = x.x + (w.x - x.x) * a;
        o.y = x.y + (w.y - x.y) * a;
        o.z = x.z + (w.z - x.z) * a;
        o.w = x.w + (w.w - x.w) * a;
        __stcs(((float4*)out) + gi, o);
    }
}

extern "C" void kernel_launch(void* const* d_in, const int* in_sizes, int n_in,
                              void* d_out, int out_size)
{
    (void)in_sizes; (void)n_in; (void)out_size;
    const float* query   = (const float*)d_in[0];
    const float* sp      = (const float*)d_in[1];
    const float* wq      = (const float*)d_in[2];
    const float* wk      = (const float*)d_in[3];
    const float* wv      = (const float*)d_in[4];
    const float* bq      = (const float*)d_in[5];
    const float* bk      = (const float*)d_in[6];
    const float* bv      = (const float*)d_in[7];
    const float* wo      = (const float*)d_in[8];
    const float* bo      = (const float*)d_in[9];
    const float* w_write = (const float*)d_in[10];
    const float* b_write = (const float*)d_in[11];
    const float* w_a1    = (const float*)d_in[12];
    const float* b_a1    = (const float*)d_in[13];
    const float* w_a2    = (const float*)d_in[14];
    const float* b_a2    = (const float*)d_in[15];
    float* out = (float*)d_out;

    k1_attn<<<Bv, 256, 32768>>>(query, sp, wq, wk, wv, bq, bk, bv, wo, bo,
                                w_write, b_write, w_a1, b_a1);
    k2_addr<<<Bv / 8, 256>>>(w_a2, b_a2);
    k3_write<<<(Bv * Sv * Dv / 4) / 512, 256>>>(sp, out);
}

// round 6
// speedup vs baseline: 1.0997x; 1.0177x over previous
#include <cuda_runtime.h>
#include <math.h>

#define Bv 1024
#define Sv 2048
#define Dv 64
#define Hv 4
#define HDv 16

// Scratch (no cudaMalloc allowed) — static device globals.
__device__ float g_hbuf[Bv * 128];        // relu(value @ w_a1.T + b_a1)
__device__ float g_wvbuf[Bv * Dv];        // write_value per batch
__device__ float g_ebuf[(size_t)Bv * Sv]; // NORMALIZED address a[b,s]

__device__ __forceinline__ void cp_async16(void* smem_dst, const void* gsrc) {
    unsigned sd = (unsigned)__cvta_generic_to_shared(smem_dst);
    asm volatile("cp.async.cg.shared.global [%0], [%1], 16;\n"
                 :: "r"(sd), "l"(gsrc) : "memory");
}
#define CP_COMMIT() asm volatile("cp.async.commit_group;\n" ::: "memory")
#define CP_WAIT3()  asm volatile("cp.async.wait_group 3;\n" ::: "memory")
#define CP_WAIT0()  asm volatile("cp.async.wait_group 0;\n" ::: "memory")

// ---------------------------------------------------------------------------
// K1: per-batch attention pass. One CTA per batch, 256 threads = 8 warps.
// PER-WARP DECOUPLED PIPELINE: warp w owns rows [w*256, w*256+256), processed
// as 64 chunks of 4 rows. Each warp has a private 5-stage smem ring
// (stage = 4 rows x 68 floats, padded for conflict-free LDS.128). Each lane
// cp.asyncs exactly the two float4s it will later read (its group's row,
// dims {4*sub..4*sub+3} and {32+4*sub..32+4*sub+3}), so cp.async.wait_group
// alone gives visibility — NO barriers in the main loop. In-flight: 4 chunks
// x 1KB per warp = 64KB/SM at 16 warps.
// ---------------------------------------------------------------------------
__global__ __launch_bounds__(256, 2) void k1_attn(
    const float* __restrict__ query, const float* __restrict__ sp,
    const float* __restrict__ wq, const float* __restrict__ wk,
    const float* __restrict__ wv, const float* __restrict__ bq,
    const float* __restrict__ bk, const float* __restrict__ bv,
    const float* __restrict__ wo, const float* __restrict__ bo,
    const float* __restrict__ w_write, const float* __restrict__ b_write,
    const float* __restrict__ w_a1, const float* __restrict__ b_a1)
{
    extern __shared__ float dyn[];   // 8 warps * 5 stages * 272 floats = 10880 floats (43.5KB)
                                     // aliased as the partial-combine buffer in the epilogue
    __shared__ float s_q[Dv];
    __shared__ float s_qv[Dv];
    __shared__ float s_qk[Hv * Dv];
    __shared__ float s_c[Hv];
    __shared__ float s_pl[32 * Hv];
    __shared__ float s_wvec[Hv * Dv];
    __shared__ float s_ctx[Dv];
    __shared__ float s_val[Dv];

    const int b = blockIdx.x;
    const int t = threadIdx.x;
    const int warp = t >> 5, lane = t & 31;
    const int g = lane >> 3, sub = lane & 7;
    const float* spb = sp + (size_t)b * Sv * Dv;

    float* wbase = dyn + warp * (5 * 272);          // this warp's private ring
    const float* src0 = spb + ((size_t)warp * 256 + g) * 64 + sub * 4;

    // ---- prologue: issue chunks 0..3 (4 rows = 1KB each; 2 cp.async/lane) ----
#pragma unroll
    for (int c = 0; c < 4; c++) {
        float* dst = wbase + c * 272 + g * 68 + sub * 4;
        const float* src = src0 + (size_t)c * 4 * 64;
        cp_async16(dst, src);
        cp_async16(dst + 32, src + 32);
        CP_COMMIT();
    }

    // ---- q projection (overlaps with in-flight loads) ----
    if (t < Dv) s_q[t] = query[(size_t)b * Dv + t];
    __syncthreads();
    if (t < Dv) {
        float acc = bq[t];
        const float* wr = wq + t * Dv;
#pragma unroll
        for (int j = 0; j < Dv; j++) acc += __ldg(wr + j) * s_q[j];
        s_qv[t] = acc;
    }
    __syncthreads();

    // ---- folded score vectors: qk_h[j] = 0.25 * sum_t qv[16h+t]*wk[16h+t,j] ----
    {
        const int h = t >> 6, j = t & 63;
        float acc = 0.f;
#pragma unroll
        for (int tt = 0; tt < HDv; tt++)
            acc += s_qv[h * HDv + tt] * __ldg(&wk[(h * HDv + tt) * Dv + j]);
        s_qk[h * Dv + j] = 0.25f * acc;
        if (t < Hv) {
            float c = 0.f;
#pragma unroll
            for (int tt = 0; tt < HDv; tt++) c += s_qv[t * HDv + tt] * __ldg(&bk[t * HDv + tt]);
            s_c[t] = 0.25f * c;
        }
    }
    __syncthreads();

    // lane's dims: k<4 -> 4*sub+k ; k>=4 -> 32+4*sub+(k-4)
    float qkr[Hv][8];
#pragma unroll
    for (int h = 0; h < Hv; h++)
#pragma unroll
        for (int k = 0; k < 8; k++) {
            int d = (k < 4) ? (4 * sub + k) : (32 + 4 * sub + k - 4);
            qkr[h][k] = s_qk[h * Dv + d];
        }
    float cst[Hv];
#pragma unroll
    for (int h = 0; h < Hv; h++) cst[h] = s_c[h];

    float u[Hv][8];
    float ls[Hv];
#pragma unroll
    for (int h = 0; h < Hv; h++) {
        ls[h] = 0.f;
#pragma unroll
        for (int k = 0; k < 8; k++) u[h][k] = 0.f;
    }

    // ---- main loop: 64 chunks, per-warp pipeline, NO barriers ----
#pragma unroll 1
    for (int c = 0; c < 64; c++) {
        const int st = c % 5;
        CP_WAIT3();                      // oldest (chunk c) complete for THIS thread

        const float4* tp = (const float4*)(wbase + st * 272);
        float4 a0 = tp[g * 17 + sub];        // dims 4*sub..4*sub+3
        float4 a1 = tp[g * 17 + 8 + sub];    // dims 32+4*sub..+3
        float xA[8] = {a0.x, a0.y, a0.z, a0.w, a1.x, a1.y, a1.z, a1.w};

        float sc[Hv];
#pragma unroll
        for (int h = 0; h < Hv; h++) {
            float sa = 0.f;
#pragma unroll
            for (int k = 0; k < 8; k++) sa += qkr[h][k] * xA[k];
            sc[h] = sa;
        }
#pragma unroll
        for (int off = 1; off < 8; off <<= 1) {
#pragma unroll
            for (int h = 0; h < Hv; h++)
                sc[h] += __shfl_xor_sync(0xffffffffu, sc[h], off);
        }
#pragma unroll
        for (int h = 0; h < Hv; h++) {
            float p = __expf(sc[h] + cst[h]);
            ls[h] += p;
#pragma unroll
            for (int k = 0; k < 8; k++) u[h][k] += p * xA[k];
        }

        // issue chunk c+4 into stage (c+4)%5 (its chunk c-1 slot, already consumed)
        const int nc = c + 4;
        if (nc < 64) {
            float* dst = wbase + (nc % 5) * 272 + g * 68 + sub * 4;
            const float* src = src0 + (size_t)nc * 4 * 64;
            cp_async16(dst, src);
            cp_async16(dst + 32, src + 32);
        }
        CP_COMMIT();                     // uniform group count even when empty
    }
    CP_WAIT0();
    __syncthreads();

    // ---- combine 32 group partials (dyn aliased; needs 8192 floats) ----
    float* s_part = dyn;
    const int pg = warp * 4 + g;
    if (sub == 0) {
#pragma unroll
        for (int h = 0; h < Hv; h++) s_pl[pg * 4 + h] = ls[h];
    }
#pragma unroll
    for (int h = 0; h < Hv; h++)
#pragma unroll
        for (int k = 0; k < 8; k++) {
            int d = (k < 4) ? (4 * sub + k) : (32 + 4 * sub + k - 4);
            s_part[(pg * 4 + h) * 64 + d] = u[h][k];
        }
    __syncthreads();
    {
        const int h = t >> 6, d = t & 63;
        float U = 0.f;
#pragma unroll
        for (int p = 0; p < 32; p++) U += s_part[(p * 4 + h) * 64 + d];
        float L = 0.f;
#pragma unroll
        for (int p = 0; p < 32; p++) L += s_pl[p * 4 + h];
        s_wvec[h * 64 + d] = U / L;   // attn-weighted mean of sp rows
    }
    __syncthreads();

    // ---- tiny per-batch matvec chain (weights straight from global/L2) ----
    if (t < Dv) {
        float acc = bv[t];
        const int h = t >> 4;
        const float* wr = wv + t * Dv;
#pragma unroll
        for (int j = 0; j < Dv; j++) acc += __ldg(wr + j) * s_wvec[h * 64 + j];
        s_ctx[t] = acc;
    }
    __syncthreads();
    if (t < Dv) {
        float acc = bo[t];
        const float* wr = wo + t * Dv;
#pragma unroll
        for (int j = 0; j < Dv; j++) acc += __ldg(wr + j) * s_ctx[j];
        s_val[t] = acc;
    }
    __syncthreads();
    if (t < 128) {
        float acc = b_a1[t];
        const float* wr = w_a1 + t * Dv;
#pragma unroll
        for (int j = 0; j < Dv; j++) acc += __ldg(wr + j) * s_val[j];
        g_hbuf[(size_t)b * 128 + t] = fmaxf(acc, 0.f);
    }
    if (t >= 128 && t < 128 + Dv) {
        const int o = t - 128;
        float acc = b_write[o];
        const float* wr = w_write + o * Dv;
#pragma unroll
        for (int j = 0; j < Dv; j++) acc += __ldg(wr + j) * s_val[j];
        g_wvbuf[(size_t)b * Dv + o] = acc;
    }
}

// ---------------------------------------------------------------------------
// K2: address logits GEMM (1024 x 2048 x 128) + softmax. Writes NORMALIZED
// address a[b,s] into g_ebuf (the CTA owns the full per-batch denominator).
// ---------------------------------------------------------------------------
__global__ __launch_bounds__(256) void k2_addr(const float* __restrict__ w_a2,
                                               const float* __restrict__ b_a2)
{
    const int b0 = blockIdx.x * 8;
    const int t = threadIdx.x;
    __shared__ float hs[8 * 128];
    __shared__ float sden[8];

    for (int idx = t; idx < 1024; idx += 256) hs[idx] = g_hbuf[(size_t)b0 * 128 + idx];
    if (t < 8) sden[t] = 0.f;
    __syncthreads();

    float acc[8][8];
#pragma unroll
    for (int r = 0; r < 8; r++)
#pragma unroll
        for (int bb = 0; bb < 8; bb++) acc[r][bb] = 0.f;

    const float4* w4 = (const float4*)w_a2;
    const float4* h4 = (const float4*)hs;
#pragma unroll 1
    for (int k8 = 0; k8 < 16; k8++) {
        float4 ha[8], hb[8];
#pragma unroll
        for (int bb = 0; bb < 8; bb++) {
            ha[bb] = h4[bb * 32 + 2 * k8];
            hb[bb] = h4[bb * 32 + 2 * k8 + 1];
        }
#pragma unroll
        for (int r = 0; r < 8; r++) {
            const int s = t + 256 * r;
            float4 wa = w4[(size_t)s * 32 + 2 * k8];
            float4 wb = w4[(size_t)s * 32 + 2 * k8 + 1];
#pragma unroll
            for (int bb = 0; bb < 8; bb++) {
                acc[r][bb] += wa.x * ha[bb].x + wa.y * ha[bb].y +
                              wa.z * ha[bb].z + wa.w * ha[bb].w +
                              wb.x * hb[bb].x + wb.y * hb[bb].y +
                              wb.z * hb[bb].z + wb.w * hb[bb].w;
            }
        }
    }

    // pass 1: per-batch exp-sum (logits small -> safe without max-sub)
    float psum[8];
#pragma unroll
    for (int bb = 0; bb < 8; bb++) psum[bb] = 0.f;
#pragma unroll
    for (int r = 0; r < 8; r++) {
        const float ba = b_a2[t + 256 * r];
#pragma unroll
        for (int bb = 0; bb < 8; bb++) psum[bb] += __expf(acc[r][bb] + ba);
    }
#pragma unroll
    for (int off = 16; off; off >>= 1)
#pragma unroll
        for (int bb = 0; bb < 8; bb++)
            psum[bb] += __shfl_xor_sync(0xffffffffu, psum[bb], off);
    if ((t & 31) == 0) {
#pragma unroll
        for (int bb = 0; bb < 8; bb++) atomicAdd(&sden[bb], psum[bb]);
    }
    __syncthreads();

    float inv[8];
#pragma unroll
    for (int bb = 0; bb < 8; bb++) inv[bb] = 1.f / sden[bb];

    // pass 2: recompute exp (deterministic), write normalized a
#pragma unroll
    for (int r = 0; r < 8; r++) {
        const int s = t + 256 * r;
        const float ba = b_a2[s];
#pragma unroll
        for (int bb = 0; bb < 8; bb++)
            g_ebuf[(size_t)(b0 + bb) * Sv + s] = __expf(acc[r][bb] + ba) * inv[bb];
    }
}

// ---------------------------------------------------------------------------
// K3: out[b,s,:] = sp + (write_value - sp) * a[b,s]. Streaming, ILP 4.
// ---------------------------------------------------------------------------
__global__ __launch_bounds__(256) void k3_write(const float* __restrict__ sp,
                                                float* __restrict__ out)
{
    const size_t base = (size_t)blockIdx.x * 1024 + threadIdx.x;  // float4 units
#pragma unroll
    for (int j = 0; j < 4; j++) {
        const size_t gi = base + (size_t)j * 256;
        const size_t row = gi >> 4;
        const int b = (int)(row >> 11);
        const float a = __ldg(&g_ebuf[row]);
        const float4 x = __ldcs(((const float4*)sp) + gi);
        const float4 w = __ldg(((const float4*)g_wvbuf) + (size_t)b * 16 + (gi & 15));
        float4 o;
        o.x = x.x + (w.x - x.x) * a;
        o.y = x.y + (w.y - x.y) * a;
        o.z = x.z + (w.z - x.z) * a;
        o.w = x.w + (w.w - x.w) * a;
        __stcs(((float4*)out) + gi, o);
    }
}

extern "C" void kernel_launch(void* const* d_in, const int* in_sizes, int n_in,
                              void* d_out, int out_size)
{
    (void)in_sizes; (void)n_in; (void)out_size;
    const float* query   = (const float*)d_in[0];
    const float* sp      = (const float*)d_in[1];
    const float* wq      = (const float*)d_in[2];
    const float* wk      = (const float*)d_in[3];
    const float* wv      = (const float*)d_in[4];
    const float* bq      = (const float*)d_in[5];
    const float* bk      = (const float*)d_in[6];
    const float* bv      = (const float*)d_in[7];
    const float* wo      = (const float*)d_in[8];
    const float* bo      = (const float*)d_in[9];
    const float* w_write = (const float*)d_in[10];
    const float* b_write = (const float*)d_in[11];
    const float* w_a1    = (const float*)d_in[12];
    const float* b_a1    = (const float*)d_in[13];
    const float* w_a2    = (const float*)d_in[14];
    const float* b_a2    = (const float*)d_in[15];
    float* out = (float*)d_out;

    k1_attn<<<Bv, 256, 43520>>>(query, sp, wq, wk, wv, bq, bk, bv, wo, bo,
                                w_write, b_write, w_a1, b_a1);
    k2_addr<<<Bv / 8, 256>>>(w_a2, b_a2);
    k3_write<<<(Bv * Sv * Dv / 4) / 1024, 256>>>(sp, out);
}

// round 7
// speedup vs baseline: 1.1393x; 1.0360x over previous
#include <cuda_runtime.h>
#include <math.h>

#define Bv 1024
#define Sv 2048
#define Dv 64
#define Hv 4
#define HDv 16

#define NSTAGE 11      // smem ring stages per warp
#define LOOKAHEAD 10   // chunks in flight

// Scratch (no cudaMalloc allowed) — static device globals.
__device__ float g_hbuf[Bv * 128];        // relu(value @ w_a1.T + b_a1)
__device__ float g_wvbuf[Bv * Dv];        // write_value per batch
__device__ float g_ebuf[(size_t)Bv * Sv]; // NORMALIZED address a[b,s]

__device__ __forceinline__ void cp_async16(void* smem_dst, const void* gsrc) {
    unsigned sd = (unsigned)__cvta_generic_to_shared(smem_dst);
    asm volatile("cp.async.cg.shared.global [%0], [%1], 16;\n"
                 :: "r"(sd), "l"(gsrc) : "memory");
}
#define CP_COMMIT() asm volatile("cp.async.commit_group;\n" ::: "memory")
#define CP_WAIT9()  asm volatile("cp.async.wait_group 9;\n" ::: "memory")
#define CP_WAIT0()  asm volatile("cp.async.wait_group 0;\n" ::: "memory")

// ---------------------------------------------------------------------------
// K1: per-batch attention pass. One CTA per batch, 256 threads = 8 warps.
// Per-warp decoupled pipeline, DEPTH 10: warp w owns rows [w*256, w*256+256)
// as 64 chunks of 4 rows; private 11-stage smem ring (stage = 4 rows x 68
// floats, padded for conflict-free LDS.128). Each lane cp.asyncs exactly the
// two float4s it later reads, so cp.async.wait_group alone gives visibility —
// no barriers in the main loop. In-flight: 10 chunks x 1KB per warp =
// 160KB/SM at 16 warps (R5's 4-chunk ring exposed ~6000-cycle effective
// latency; depth 10 amortizes it to ~600/iter).
// ---------------------------------------------------------------------------
__global__ __launch_bounds__(256, 2) void k1_attn(
    const float* __restrict__ query, const float* __restrict__ sp,
    const float* __restrict__ wq, const float* __restrict__ wk,
    const float* __restrict__ wv, const float* __restrict__ bq,
    const float* __restrict__ bk, const float* __restrict__ bv,
    const float* __restrict__ wo, const float* __restrict__ bo,
    const float* __restrict__ w_write, const float* __restrict__ b_write,
    const float* __restrict__ w_a1, const float* __restrict__ b_a1)
{
    extern __shared__ float dyn[];   // 8 warps * 11 stages * 272 floats = 23936 floats (95.7KB)
                                     // aliased as the partial-combine buffer in the epilogue
    __shared__ float s_q[Dv];
    __shared__ float s_qv[Dv];
    __shared__ float s_qk[Hv * Dv];
    __shared__ float s_c[Hv];
    __shared__ float s_pl[32 * Hv];
    __shared__ float s_wvec[Hv * Dv];
    __shared__ float s_ctx[Dv];
    __shared__ float s_val[Dv];

    const int b = blockIdx.x;
    const int t = threadIdx.x;
    const int warp = t >> 5, lane = t & 31;
    const int g = lane >> 3, sub = lane & 7;
    const float* spb = sp + (size_t)b * Sv * Dv;

    float* wbase = dyn + warp * (NSTAGE * 272);     // this warp's private ring
    float* lbase = wbase + g * 68 + sub * 4;        // this lane's write slot (per stage)
    const float* src0 = spb + ((size_t)warp * 256 + g) * 64 + sub * 4;

    // ---- prologue: issue chunks 0..9 (4 rows = 1KB each; 2 cp.async/lane) ----
#pragma unroll
    for (int c = 0; c < LOOKAHEAD; c++) {
        float* dst = lbase + c * 272;
        const float* src = src0 + (size_t)c * 256;
        cp_async16(dst, src);
        cp_async16(dst + 32, src + 32);
        CP_COMMIT();
    }

    // ---- q projection (overlaps with in-flight loads) ----
    if (t < Dv) s_q[t] = query[(size_t)b * Dv + t];
    __syncthreads();
    if (t < Dv) {
        float acc = bq[t];
        const float* wr = wq + t * Dv;
#pragma unroll
        for (int j = 0; j < Dv; j++) acc += __ldg(wr + j) * s_q[j];
        s_qv[t] = acc;
    }
    __syncthreads();

    // ---- folded score vectors: qk_h[j] = 0.25 * sum_t qv[16h+t]*wk[16h+t,j] ----
    {
        const int h = t >> 6, j = t & 63;
        float acc = 0.f;
#pragma unroll
        for (int tt = 0; tt < HDv; tt++)
            acc += s_qv[h * HDv + tt] * __ldg(&wk[(h * HDv + tt) * Dv + j]);
        s_qk[h * Dv + j] = 0.25f * acc;
        if (t < Hv) {
            float c = 0.f;
#pragma unroll
            for (int tt = 0; tt < HDv; tt++) c += s_qv[t * HDv + tt] * __ldg(&bk[t * HDv + tt]);
            s_c[t] = 0.25f * c;
        }
    }
    __syncthreads();

    // lane's dims: k<4 -> 4*sub+k ; k>=4 -> 32+4*sub+(k-4)
    float qkr[Hv][8];
#pragma unroll
    for (int h = 0; h < Hv; h++)
#pragma unroll
        for (int k = 0; k < 8; k++) {
            int d = (k < 4) ? (4 * sub + k) : (32 + 4 * sub + k - 4);
            qkr[h][k] = s_qk[h * Dv + d];
        }
    float cst[Hv];
#pragma unroll
    for (int h = 0; h < Hv; h++) cst[h] = s_c[h];

    float u[Hv][8];
    float ls[Hv];
#pragma unroll
    for (int h = 0; h < Hv; h++) {
        ls[h] = 0.f;
#pragma unroll
        for (int k = 0; k < 8; k++) u[h][k] = 0.f;
    }

    // ---- main loop: 64 chunks, per-warp pipeline, NO barriers ----
    int st = 0;                 // stage holding chunk c
    int nst = LOOKAHEAD;        // stage for chunk c+LOOKAHEAD
#pragma unroll 1
    for (int c = 0; c < 64; c++) {
        CP_WAIT9();                      // chunk c complete for THIS thread

        // issue chunk c+10 first (enters memory system before compute)
        const int nc = c + LOOKAHEAD;
        if (nc < 64) {
            float* dst = lbase + nst * 272;
            const float* src = src0 + (size_t)nc * 256;
            cp_async16(dst, src);
            cp_async16(dst + 32, src + 32);
        }
        CP_COMMIT();                     // uniform group count even when empty

        const float4* tp = (const float4*)(wbase + st * 272);
        float4 a0 = tp[g * 17 + sub];        // dims 4*sub..4*sub+3
        float4 a1 = tp[g * 17 + 8 + sub];    // dims 32+4*sub..+3
        float xA[8] = {a0.x, a0.y, a0.z, a0.w, a1.x, a1.y, a1.z, a1.w};

        float sc[Hv];
#pragma unroll
        for (int h = 0; h < Hv; h++) {
            float sa = 0.f;
#pragma unroll
            for (int k = 0; k < 8; k++) sa += qkr[h][k] * xA[k];
            sc[h] = sa;
        }
#pragma unroll
        for (int off = 1; off < 8; off <<= 1) {
#pragma unroll
            for (int h = 0; h < Hv; h++)
                sc[h] += __shfl_xor_sync(0xffffffffu, sc[h], off);
        }
#pragma unroll
        for (int h = 0; h < Hv; h++) {
            float p = __expf(sc[h] + cst[h]);
            ls[h] += p;
#pragma unroll
            for (int k = 0; k < 8; k++) u[h][k] += p * xA[k];
        }

        if (++st == NSTAGE) st = 0;
        if (++nst == NSTAGE) nst = 0;
    }
    CP_WAIT0();
    __syncthreads();

    // ---- combine 32 group partials (dyn aliased; needs 8192 floats) ----
    float* s_part = dyn;
    const int pg = warp * 4 + g;
    if (sub == 0) {
#pragma unroll
        for (int h = 0; h < Hv; h++) s_pl[pg * 4 + h] = ls[h];
    }
#pragma unroll
    for (int h = 0; h < Hv; h++)
#pragma unroll
        for (int k = 0; k < 8; k++) {
            int d = (k < 4) ? (4 * sub + k) : (32 + 4 * sub + k - 4);
            s_part[(pg * 4 + h) * 64 + d] = u[h][k];
        }
    __syncthreads();
    {
        const int h = t >> 6, d = t & 63;
        float U = 0.f;
#pragma unroll
        for (int p = 0; p < 32; p++) U += s_part[(p * 4 + h) * 64 + d];
        float L = 0.f;
#pragma unroll
        for (int p = 0; p < 32; p++) L += s_pl[p * 4 + h];
        s_wvec[h * 64 + d] = U / L;   // attn-weighted mean of sp rows
    }
    __syncthreads();

    // ---- tiny per-batch matvec chain (weights straight from global/L2) ----
    if (t < Dv) {
        float acc = bv[t];
        const int h = t >> 4;
        const float* wr = wv + t * Dv;
#pragma unroll
        for (int j = 0; j < Dv; j++) acc += __ldg(wr + j) * s_wvec[h * 64 + j];
        s_ctx[t] = acc;
    }
    __syncthreads();
    if (t < Dv) {
        float acc = bo[t];
        const float* wr = wo + t * Dv;
#pragma unroll
        for (int j = 0; j < Dv; j++) acc += __ldg(wr + j) * s_ctx[j];
        s_val[t] = acc;
    }
    __syncthreads();
    if (t < 128) {
        float acc = b_a1[t];
        const float* wr = w_a1 + t * Dv;
#pragma unroll
        for (int j = 0; j < Dv; j++) acc += __ldg(wr + j) * s_val[j];
        g_hbuf[(size_t)b * 128 + t] = fmaxf(acc, 0.f);
    }
    if (t >= 128 && t < 128 + Dv) {
        const int o = t - 128;
        float acc = b_write[o];
        const float* wr = w_write + o * Dv;
#pragma unroll
        for (int j = 0; j < Dv; j++) acc += __ldg(wr + j) * s_val[j];
        g_wvbuf[(size_t)b * Dv + o] = acc;
    }
}

// ---------------------------------------------------------------------------
// K2: address logits GEMM (1024 x 2048 x 128) + softmax. Writes NORMALIZED
// address a[b,s] into g_ebuf (the CTA owns the full per-batch denominator).
// ---------------------------------------------------------------------------
__global__ __launch_bounds__(256) void k2_addr(const float* __restrict__ w_a2,
                                               const float* __restrict__ b_a2)
{
    const int b0 = blockIdx.x * 8;
    const int t = threadIdx.x;
    __shared__ float hs[8 * 128];
    __shared__ float sden[8];

    for (int idx = t; idx < 1024; idx += 256) hs[idx] = g_hbuf[(size_t)b0 * 128 + idx];
    if (t < 8) sden[t] = 0.f;
    __syncthreads();

    float acc[8][8];
#pragma unroll
    for (int r = 0; r < 8; r++)
#pragma unroll
        for (int bb = 0; bb < 8; bb++) acc[r][bb] = 0.f;

    const float4* w4 = (const float4*)w_a2;
    const float4* h4 = (const float4*)hs;
#pragma unroll 1
    for (int k8 = 0; k8 < 16; k8++) {
        float4 ha[8], hb[8];
#pragma unroll
        for (int bb = 0; bb < 8; bb++) {
            ha[bb] = h4[bb * 32 + 2 * k8];
            hb[bb] = h4[bb * 32 + 2 * k8 + 1];
        }
#pragma unroll
        for (int r = 0; r < 8; r++) {
            const int s = t + 256 * r;
            float4 wa = w4[(size_t)s * 32 + 2 * k8];
            float4 wb = w4[(size_t)s * 32 + 2 * k8 + 1];
#pragma unroll
            for (int bb = 0; bb < 8; bb++) {
                acc[r][bb] += wa.x * ha[bb].x + wa.y * ha[bb].y +
                              wa.z * ha[bb].z + wa.w * ha[bb].w +
                              wb.x * hb[bb].x + wb.y * hb[bb].y +
                              wb.z * hb[bb].z + wb.w * hb[bb].w;
            }
        }
    }

    // pass 1: per-batch exp-sum (logits small -> safe without max-sub)
    float psum[8];
#pragma unroll
    for (int bb = 0; bb < 8; bb++) psum[bb] = 0.f;
#pragma unroll
    for (int r = 0; r < 8; r++) {
        const float ba = b_a2[t + 256 * r];
#pragma unroll
        for (int bb = 0; bb < 8; bb++) psum[bb] += __expf(acc[r][bb] + ba);
    }
#pragma unroll
    for (int off = 16; off; off >>= 1)
#pragma unroll
        for (int bb = 0; bb < 8; bb++)
            psum[bb] += __shfl_xor_sync(0xffffffffu, psum[bb], off);
    if ((t & 31) == 0) {
#pragma unroll
        for (int bb = 0; bb < 8; bb++) atomicAdd(&sden[bb], psum[bb]);
    }
    __syncthreads();

    float inv[8];
#pragma unroll
    for (int bb = 0; bb < 8; bb++) inv[bb] = 1.f / sden[bb];

    // pass 2: recompute exp (deterministic), write normalized a
#pragma unroll
    for (int r = 0; r < 8; r++) {
        const int s = t + 256 * r;
        const float ba = b_a2[s];
#pragma unroll
        for (int bb = 0; bb < 8; bb++)
            g_ebuf[(size_t)(b0 + bb) * Sv + s] = __expf(acc[r][bb] + ba) * inv[bb];
    }
}

// ---------------------------------------------------------------------------
// K3: out[b,s,:] = sp + (write_value - sp) * a[b,s]. Streaming, ILP 4.
// ---------------------------------------------------------------------------
__global__ __launch_bounds__(256) void k3_write(const float* __restrict__ sp,
                                                float* __restrict__ out)
{
    const size_t base = (size_t)blockIdx.x * 1024 + threadIdx.x;  // float4 units
#pragma unroll
    for (int j = 0; j < 4; j++) {
        const size_t gi = base + (size_t)j * 256;
        const size_t row = gi >> 4;
        const int b = (int)(row >> 11);
        const float a = __ldg(&g_ebuf[row]);
        const float4 x = __ldcs(((const float4*)sp) + gi);
        const float4 w = __ldg(((const float4*)g_wvbuf) + (size_t)b * 16 + (gi & 15));
        float4 o;
        o.x = x.x + (w.x - x.x) * a;
        o.y = x.y + (w.y - x.y) * a;
        o.z = x.z + (w.z - x.z) * a;
        o.w = x.w + (w.w - x.w) * a;
        __stcs(((float4*)out) + gi, o);
    }
}

extern "C" void kernel_launch(void* const* d_in, const int* in_sizes, int n_in,
                              void* d_out, int out_size)
{
    (void)in_sizes; (void)n_in; (void)out_size;
    const float* query   = (const float*)d_in[0];
    const float* sp      = (const float*)d_in[1];
    const float* wq      = (const float*)d_in[2];
    const float* wk      = (const float*)d_in[3];
    const float* wv      = (const float*)d_in[4];
    const float* bq      = (const float*)d_in[5];
    const float* bk      = (const float*)d_in[6];
    const float* bv      = (const float*)d_in[7];
    const float* wo      = (const float*)d_in[8];
    const float* bo      = (const float*)d_in[9];
    const float* w_write = (const float*)d_in[10];
    const float* b_write = (const float*)d_in[11];
    const float* w_a1    = (const float*)d_in[12];
    const float* b_a1    = (const float*)d_in[13];
    const float* w_a2    = (const float*)d_in[14];
    const float* b_a2    = (const float*)d_in[15];
    float* out = (float*)d_out;

    const int k1_dyn = 8 * NSTAGE * 272 * (int)sizeof(float);   // 95744 bytes
    // Attribute set: host-side function-state call (no alloc, no sync) —
    // legal during graph capture; idempotent and deterministic.
    cudaFuncSetAttribute(k1_attn, cudaFuncAttributeMaxDynamicSharedMemorySize, k1_dyn);

    k1_attn<<<Bv, 256, k1_dyn>>>(query, sp, wq, wk, wv, bq, bk, bv, wo, bo,
                                 w_write, b_write, w_a1, b_a1);
    k2_addr<<<Bv / 8, 256>>>(w_a2, b_a2);
    k3_write<<<(Bv * Sv * Dv / 4) / 1024, 256>>>(sp, out);
}

// round 8
// speedup vs baseline: 1.1485x; 1.0080x over previous
#include <cuda_runtime.h>
#include <math.h>

#define Bv 1024
#define Sv 2048
#define Dv 64
#define Hv 4
#define HDv 16

#define NSTAGE 11      // smem ring stages per warp
#define LOOKAHEAD 10   // chunks in flight

// Scratch (no cudaMalloc allowed) — static device globals.
__device__ float g_hbuf[Bv * 128];        // relu(value @ w_a1.T + b_a1)
__device__ float g_wvbuf[Bv * Dv];        // write_value per batch
__device__ float g_ebuf[(size_t)Bv * Sv]; // NORMALIZED address a[b,s]

__device__ __forceinline__ void cp_async16(void* smem_dst, const void* gsrc) {
    unsigned sd = (unsigned)__cvta_generic_to_shared(smem_dst);
    asm volatile("cp.async.cg.shared.global [%0], [%1], 16;\n"
                 :: "r"(sd), "l"(gsrc) : "memory");
}
#define CP_COMMIT() asm volatile("cp.async.commit_group;\n" ::: "memory")
#define CP_WAIT9()  asm volatile("cp.async.wait_group 9;\n" ::: "memory")
#define CP_WAIT0()  asm volatile("cp.async.wait_group 0;\n" ::: "memory")

// ---- packed f32x2 helpers (sm_103a paired-FP32 pipe) ----
typedef unsigned long long u64t;
__device__ __forceinline__ u64t pk2(float a, float b) {
    u64t r; asm("mov.b64 %0, {%1, %2};" : "=l"(r) : "f"(a), "f"(b)); return r;
}
__device__ __forceinline__ void unpk2(float& a, float& b, u64t p) {
    asm("mov.b64 {%0, %1}, %2;" : "=f"(a), "=f"(b) : "l"(p));
}
__device__ __forceinline__ u64t mul2(u64t a, u64t b) {
    u64t r; asm("mul.rn.f32x2 %0, %1, %2;" : "=l"(r) : "l"(a), "l"(b)); return r;
}
__device__ __forceinline__ void fma2(u64t& d, u64t a, u64t b) {
    asm("fma.rn.f32x2 %0, %1, %2, %0;" : "+l"(d) : "l"(a), "l"(b));
}

#define LOG2E 1.4426950408889634f

// ---------------------------------------------------------------------------
// K1: per-batch attention pass. One CTA per batch, 256 threads = 8 warps.
// Per-warp decoupled cp.async pipeline (depth 10, 11-stage ring) — unchanged
// from R6. New in R7 (k1 is instruction-issue bound):
//  * score + u accumulation in packed f32x2 (halves FFMA count)
//  * reduce-scatter (lane sub owns head sub&3) -> exp once per head ->
//    3-SHFL butterfly allgather; q[j] = head (sub&3)^j, a FIXED per-lane
//    permutation absorbed in the epilogue partial-store indexing.
// ---------------------------------------------------------------------------
__global__ __launch_bounds__(256, 2) void k1_attn(
    const float* __restrict__ query, const float* __restrict__ sp,
    const float* __restrict__ wq, const float* __restrict__ wk,
    const float* __restrict__ wv, const float* __restrict__ bq,
    const float* __restrict__ bk, const float* __restrict__ bv,
    const float* __restrict__ wo, const float* __restrict__ bo,
    const float* __restrict__ w_write, const float* __restrict__ b_write,
    const float* __restrict__ w_a1, const float* __restrict__ b_a1)
{
    extern __shared__ float dyn[];   // 8 warps * 11 stages * 272 floats (95.7KB)
    __shared__ float s_q[Dv];
    __shared__ float s_qv[Dv];
    __shared__ float s_qk[Hv * Dv];
    __shared__ float s_c[Hv];
    __shared__ float s_pl[32 * Hv];
    __shared__ float s_wvec[Hv * Dv];
    __shared__ float s_ctx[Dv];
    __shared__ float s_val[Dv];

    const int b = blockIdx.x;
    const int t = threadIdx.x;
    const int warp = t >> 5, lane = t & 31;
    const int g = lane >> 3, sub = lane & 7;
    const float* spb = sp + (size_t)b * Sv * Dv;

    float* wbase = dyn + warp * (NSTAGE * 272);     // this warp's private ring
    float* lbase = wbase + g * 68 + sub * 4;        // this lane's write slot (per stage)
    const float* src0 = spb + ((size_t)warp * 256 + g) * 64 + sub * 4;

    // ---- prologue: issue chunks 0..9 (4 rows = 1KB each; 2 cp.async/lane) ----
#pragma unroll
    for (int c = 0; c < LOOKAHEAD; c++) {
        float* dst = lbase + c * 272;
        const float* src = src0 + (size_t)c * 256;
        cp_async16(dst, src);
        cp_async16(dst + 32, src + 32);
        CP_COMMIT();
    }

    // ---- q projection (overlaps with in-flight loads) ----
    if (t < Dv) s_q[t] = query[(size_t)b * Dv + t];
    __syncthreads();
    if (t < Dv) {
        float acc = bq[t];
        const float* wr = wq + t * Dv;
#pragma unroll
        for (int j = 0; j < Dv; j++) acc += __ldg(wr + j) * s_q[j];
        s_qv[t] = acc;
    }
    __syncthreads();

    // ---- folded score vectors: qk_h[j] = 0.25 * sum_t qv[16h+t]*wk[16h+t,j] ----
    {
        const int h = t >> 6, j = t & 63;
        float acc = 0.f;
#pragma unroll
        for (int tt = 0; tt < HDv; tt++)
            acc += s_qv[h * HDv + tt] * __ldg(&wk[(h * HDv + tt) * Dv + j]);
        s_qk[h * Dv + j] = 0.25f * acc;
        if (t < Hv) {
            float c = 0.f;
#pragma unroll
            for (int tt = 0; tt < HDv; tt++) c += s_qv[t * HDv + tt] * __ldg(&bk[t * HDv + tt]);
            s_c[t] = 0.25f * c;
        }
    }
    __syncthreads();

    // lane's dims: k<4 -> 4*sub+k ; k>=4 -> 32+4*sub+(k-4)
    // qk packed: qk2[h][kk] = (qk[h][2kk], qk[h][2kk+1]) in the lane-dim order
    u64t qk2[Hv][4];
#pragma unroll
    for (int h = 0; h < Hv; h++) {
        float r[8];
#pragma unroll
        for (int k = 0; k < 8; k++) {
            int d = (k < 4) ? (4 * sub + k) : (32 + 4 * sub + k - 4);
            r[k] = s_qk[h * Dv + d];
        }
#pragma unroll
        for (int kk = 0; kk < 4; kk++) qk2[h][kk] = pk2(r[2 * kk], r[2 * kk + 1]);
    }
    const int base = sub & 3;                 // head this lane owns post-reduction
    const float cprem = s_c[base] * LOG2E;    // folded bias for the owned head
    const bool b0 = (sub & 1) != 0;
    const bool b1 = (sub & 2) != 0;

    u64t u2[Hv][4];                            // u2[j] accumulates head (base^j)
    float ls[Hv];                              // ls[j]  accumulates head (base^j)
#pragma unroll
    for (int j = 0; j < Hv; j++) {
        ls[j] = 0.f;
#pragma unroll
        for (int kk = 0; kk < 4; kk++) u2[j][kk] = 0ull;
    }

    // ---- main loop: 64 chunks, per-warp pipeline, NO barriers ----
    int st = 0;                 // stage holding chunk c
    int nst = LOOKAHEAD;        // stage for chunk c+LOOKAHEAD
#pragma unroll 1
    for (int c = 0; c < 64; c++) {
        CP_WAIT9();                      // chunk c complete for THIS thread

        // issue chunk c+10 first (enters memory system before compute)
        const int nc = c + LOOKAHEAD;
        if (nc < 64) {
            float* dst = lbase + nst * 272;
            const float* src = src0 + (size_t)nc * 256;
            cp_async16(dst, src);
            cp_async16(dst + 32, src + 32);
        }
        CP_COMMIT();                     // uniform group count even when empty

        const float4* tp = (const float4*)(wbase + st * 272);
        float4 a0 = tp[g * 17 + sub];        // dims 4*sub..4*sub+3
        float4 a1 = tp[g * 17 + 8 + sub];    // dims 32+4*sub..+3
        u64t xp[4];
        xp[0] = pk2(a0.x, a0.y); xp[1] = pk2(a0.z, a0.w);
        xp[2] = pk2(a1.x, a1.y); xp[3] = pk2(a1.z, a1.w);

        // score partials, packed: v[h] = dot(qk[h], x) over this lane's 8 dims
        float v[Hv];
#pragma unroll
        for (int h = 0; h < Hv; h++) {
            u64t acc = mul2(qk2[h][0], xp[0]);
            fma2(acc, qk2[h][1], xp[1]);
            fma2(acc, qk2[h][2], xp[2]);
            fma2(acc, qk2[h][3], xp[3]);
            float lo, hi; unpk2(lo, hi, acc);
            v[h] = lo + hi;
        }

        // reduce-scatter over the 8-lane group: lane ends with full sum of
        // head (sub&3). Round ^2 (keep pair 2*b1), round ^1 (keep one),
        // round ^4 (combine the two half-group partials).
        float s0 = b1 ? v[0] : v[2];
        float s1 = b1 ? v[1] : v[3];
        float r0 = __shfl_xor_sync(0xffffffffu, s0, 2);
        float r1 = __shfl_xor_sync(0xffffffffu, s1, 2);
        float a0s = (b1 ? v[2] : v[0]) + r0;   // head 2*b1
        float a1s = (b1 ? v[3] : v[1]) + r1;   // head 2*b1+1
        float s2 = b0 ? a0s : a1s;
        float r2 = __shfl_xor_sync(0xffffffffu, s2, 1);
        float s = (b0 ? a1s : a0s) + r2;       // head sub&3, half-group sum
        s += __shfl_xor_sync(0xffffffffu, s, 4);

        // exp once per head (at its 2 owner lanes), then 3-SHFL allgather:
        // q[j] = p of head (base^j)
        float q0 = exp2f(__fmaf_rn(s, LOG2E, cprem));
        float q1 = __shfl_xor_sync(0xffffffffu, q0, 1);
        float q2 = __shfl_xor_sync(0xffffffffu, q0, 2);
        float q3 = __shfl_xor_sync(0xffffffffu, q1, 2);
        float q[4] = {q0, q1, q2, q3};

#pragma unroll
        for (int j = 0; j < Hv; j++) {
            ls[j] += q[j];
            u64t qq = pk2(q[j], q[j]);
            fma2(u2[j][0], qq, xp[0]);
            fma2(u2[j][1], qq, xp[1]);
            fma2(u2[j][2], qq, xp[2]);
            fma2(u2[j][3], qq, xp[3]);
        }

        if (++st == NSTAGE) st = 0;
        if (++nst == NSTAGE) nst = 0;
    }
    CP_WAIT0();
    __syncthreads();

    // ---- combine 32 group partials (dyn aliased; needs 8192 floats) ----
    // u2[j]/ls[j] correspond to REAL head (base^j): permute on store.
    float* s_part = dyn;
    const int pg = warp * 4 + g;
    if (sub == 0) {                 // base=0 -> identity permutation
#pragma unroll
        for (int j = 0; j < Hv; j++) s_pl[pg * 4 + j] = ls[j];
    }
#pragma unroll
    for (int j = 0; j < Hv; j++) {
        const int h = base ^ j;     // real head
#pragma unroll
        for (int kk = 0; kk < 4; kk++) {
            float lo, hi; unpk2(lo, hi, u2[j][kk]);
            int k0 = 2 * kk, k1 = 2 * kk + 1;
            int d0 = (k0 < 4) ? (4 * sub + k0) : (32 + 4 * sub + k0 - 4);
            int d1 = (k1 < 4) ? (4 * sub + k1) : (32 + 4 * sub + k1 - 4);
            s_part[(pg * 4 + h) * 64 + d0] = lo;
            s_part[(pg * 4 + h) * 64 + d1] = hi;
        }
    }
    __syncthreads();
    {
        const int h = t >> 6, d = t & 63;
        float U = 0.f;
#pragma unroll
        for (int p = 0; p < 32; p++) U += s_part[(p * 4 + h) * 64 + d];
        float L = 0.f;
#pragma unroll
        for (int p = 0; p < 32; p++) L += s_pl[p * 4 + h];
        s_wvec[h * 64 + d] = U / L;   // attn-weighted mean of sp rows
    }
    __syncthreads();

    // ---- tiny per-batch matvec chain (weights straight from global/L2) ----
    if (t < Dv) {
        float acc = bv[t];
        const int h = t >> 4;
        const float* wr = wv + t * Dv;
#pragma unroll
        for (int j = 0; j < Dv; j++) acc += __ldg(wr + j) * s_wvec[h * 64 + j];
        s_ctx[t] = acc;
    }
    __syncthreads();
    if (t < Dv) {
        float acc = bo[t];
        const float* wr = wo + t * Dv;
#pragma unroll
        for (int j = 0; j < Dv; j++) acc += __ldg(wr + j) * s_ctx[j];
        s_val[t] = acc;
    }
    __syncthreads();
    if (t < 128) {
        float acc = b_a1[t];
        const float* wr = w_a1 + t * Dv;
#pragma unroll
        for (int j = 0; j < Dv; j++) acc += __ldg(wr + j) * s_val[j];
        g_hbuf[(size_t)b * 128 + t] = fmaxf(acc, 0.f);
    }
    if (t >= 128 && t < 128 + Dv) {
        const int o = t - 128;
        float acc = b_write[o];
        const float* wr = w_write + o * Dv;
#pragma unroll
        for (int j = 0; j < Dv; j++) acc += __ldg(wr + j) * s_val[j];
        g_wvbuf[(size_t)b * Dv + o] = acc;
    }
}

// ---------------------------------------------------------------------------
// K2: address logits GEMM (1024 x 2048 x 128) + softmax. Writes NORMALIZED
// address a[b,s] into g_ebuf (the CTA owns the full per-batch denominator).
// ---------------------------------------------------------------------------
__global__ __launch_bounds__(256) void k2_addr(const float* __restrict__ w_a2,
                                               const float* __restrict__ b_a2)
{
    const int b0 = blockIdx.x * 8;
    const int t = threadIdx.x;
    __shared__ float hs[8 * 128];
    __shared__ float sden[8];

    for (int idx = t; idx < 1024; idx += 256) hs[idx] = g_hbuf[(size_t)b0 * 128 + idx];
    if (t < 8) sden[t] = 0.f;
    __syncthreads();

    float acc[8][8];
#pragma unroll
    for (int r = 0; r < 8; r++)
#pragma unroll
        for (int bb = 0; bb < 8; bb++) acc[r][bb] = 0.f;

    const float4* w4 = (const float4*)w_a2;
    const float4* h4 = (const float4*)hs;
#pragma unroll 1
    for (int k8 = 0; k8 < 16; k8++) {
        float4 ha[8], hb[8];
#pragma unroll
        for (int bb = 0; bb < 8; bb++) {
            ha[bb] = h4[bb * 32 + 2 * k8];
            hb[bb] = h4[bb * 32 + 2 * k8 + 1];
        }
#pragma unroll
        for (int r = 0; r < 8; r++) {
            const int s = t + 256 * r;
            float4 wa = w4[(size_t)s * 32 + 2 * k8];
            float4 wb = w4[(size_t)s * 32 + 2 * k8 + 1];
#pragma unroll
            for (int bb = 0; bb < 8; bb++) {
                acc[r][bb] += wa.x * ha[bb].x + wa.y * ha[bb].y +
                              wa.z * ha[bb].z + wa.w * ha[bb].w +
                              wb.x * hb[bb].x + wb.y * hb[bb].y +
                              wb.z * hb[bb].z + wb.w * hb[bb].w;
            }
        }
    }

    // pass 1: per-batch exp-sum (logits small -> safe without max-sub)
    float psum[8];
#pragma unroll
    for (int bb = 0; bb < 8; bb++) psum[bb] = 0.f;
#pragma unroll
    for (int r = 0; r < 8; r++) {
        const float ba = b_a2[t + 256 * r];
#pragma unroll
        for (int bb = 0; bb < 8; bb++) psum[bb] += __expf(acc[r][bb] + ba);
    }
#pragma unroll
    for (int off = 16; off; off >>= 1)
#pragma unroll
        for (int bb = 0; bb < 8; bb++)
            psum[bb] += __shfl_xor_sync(0xffffffffu, psum[bb], off);
    if ((t & 31) == 0) {
#pragma unroll
        for (int bb = 0; bb < 8; bb++) atomicAdd(&sden[bb], psum[bb]);
    }
    __syncthreads();

    float inv[8];
#pragma unroll
    for (int bb = 0; bb < 8; bb++) inv[bb] = 1.f / sden[bb];

    // pass 2: recompute exp (deterministic), write normalized a
#pragma unroll
    for (int r = 0; r < 8; r++) {
        const int s = t + 256 * r;
        const float ba = b_a2[s];
#pragma unroll
        for (int bb = 0; bb < 8; bb++)
            g_ebuf[(size_t)(b0 + bb) * Sv + s] = __expf(acc[r][bb] + ba) * inv[bb];
    }
}

// ---------------------------------------------------------------------------
// K3: out[b,s,:] = sp + (write_value - sp) * a[b,s]. Streaming, ILP 4.
// ---------------------------------------------------------------------------
__global__ __launch_bounds__(256) void k3_write(const float* __restrict__ sp,
                                                float* __restrict__ out)
{
    const size_t base = (size_t)blockIdx.x * 1024 + threadIdx.x;  // float4 units
#pragma unroll
    for (int j = 0; j < 4; j++) {
        const size_t gi = base + (size_t)j * 256;
        const size_t row = gi >> 4;
        const int b = (int)(row >> 11);
        const float a = __ldg(&g_ebuf[row]);
        const float4 x = __ldcs(((const float4*)sp) + gi);
        const float4 w = __ldg(((const float4*)g_wvbuf) + (size_t)b * 16 + (gi & 15));
        float4 o;
        o.x = x.x + (w.x - x.x) * a;
        o.y = x.y + (w.y - x.y) * a;
        o.z = x.z + (w.z - x.z) * a;
        o.w = x.w + (w.w - x.w) * a;
        __stcs(((float4*)out) + gi, o);
    }
}

extern "C" void kernel_launch(void* const* d_in, const int* in_sizes, int n_in,
                              void* d_out, int out_size)
{
    (void)in_sizes; (void)n_in; (void)out_size;
    const float* query   = (const float*)d_in[0];
    const float* sp      = (const float*)d_in[1];
    const float* wq      = (const float*)d_in[2];
    const float* wk      = (const float*)d_in[3];
    const float* wv      = (const float*)d_in[4];
    const float* bq      = (const float*)d_in[5];
    const float* bk      = (const float*)d_in[6];
    const float* bv      = (const float*)d_in[7];
    const float* wo      = (const float*)d_in[8];
    const float* bo      = (const float*)d_in[9];
    const float* w_write = (const float*)d_in[10];
    const float* b_write = (const float*)d_in[11];
    const float* w_a1    = (const float*)d_in[12];
    const float* b_a1    = (const float*)d_in[13];
    const float* w_a2    = (const float*)d_in[14];
    const float* b_a2    = (const float*)d_in[15];
    float* out = (float*)d_out;

    const int k1_dyn = 8 * NSTAGE * 272 * (int)sizeof(float);   // 95744 bytes
    cudaFuncSetAttribute(k1_attn, cudaFuncAttributeMaxDynamicSharedMemorySize, k1_dyn);

    k1_attn<<<Bv, 256, k1_dyn>>>(query, sp, wq, wk, wv, bq, bk, bv, wo, bo,
                                 w_write, b_write, w_a1, b_a1);
    k2_addr<<<Bv / 8, 256>>>(w_a2, b_a2);
    k3_write<<<(Bv * Sv * Dv / 4) / 1024, 256>>>(sp, out);
}